// round 6
// baseline (speedup 1.0000x reference)
#include <cuda_runtime.h>
#include <cstdint>
#include <cstddef>

#define DD 4096
#define NROWS 1920

#define BM 128
#define BN 128
#define BK 16
#define NSTAGE 4
#define NTHREADS 128          // 4 warps, 2x2 grid of 64x64 warp tiles

#define ASTRIDE 20            // floats per A smem row (pad 16->20: conflict-free)
#define BSTRIDE 136           // floats per B smem row (pad 128->136: conflict-free)
#define A_STG (BM * ASTRIDE)  // 2560 floats
#define B_STG (BK * BSTRIDE)  // 2176 floats
#define SMEM_FLOATS (NSTAGE * (A_STG + B_STG))
#define SMEM_BYTES  (SMEM_FLOATS * 4)   // 75776

__constant__ float c_nodes[15] = {
    0.20778495500789848f,  0.4058451513773972f,  0.5860872354676911f,
    0.7415311855993945f,   0.8648644233597691f,  0.9491079123427585f,
    0.9914553711208126f,  -0.9914553711208126f, -0.9491079123427585f,
   -0.8648644233597691f,  -0.7415311855993945f, -0.5860872354676911f,
   -0.4058451513773972f,  -0.20778495500789848f, 0.0f
};
__constant__ float c_wk[15] = {
    0.20443294007529889f, 0.19035057806478542f, 0.1690047266392679f,
    0.14065325971552592f, 0.10479001032225019f, 0.06309209262997856f,
    0.022935322010529224f, 0.022935322010529224f, 0.06309209262997856f,
    0.10479001032225019f, 0.14065325971552592f, 0.1690047266392679f,
    0.19035057806478542f, 0.20443294007529889f, 0.20948214108472782f
};

// Scratch (__device__ globals: allocation-free rule)
__device__ __align__(128) float g_phi [(size_t)NROWS * DD];  // [m][k] tf32-rounded
__device__ __align__(128) float g_phiT[(size_t)DD * NROWS];  // [i][n] tf32-rounded
__device__ __align__(128) float g_Wr  [(size_t)DD * DD];     // W tf32-rounded
__device__ __align__(128) float g_g   [(size_t)NROWS * DD];  // [n][j] tf32-rounded

// ---------------- helpers ----------------
__device__ __forceinline__ uint32_t s2u(const void* p) {
    uint32_t a;
    asm("{ .reg .u64 t; cvta.to.shared.u64 t, %1; cvt.u32.u64 %0, t; }" : "=r"(a) : "l"(p));
    return a;
}
__device__ __forceinline__ float tf32r(float x) {
    uint32_t u;
    asm("cvt.rna.tf32.f32 %0, %1;" : "=r"(u) : "f"(x));
    return __uint_as_float(u);
}
__device__ __forceinline__ float row_t(int m) {
    return fmaf(c_nodes[m % 15], 1.0f / 256.0f, (float)(2 * (m / 15) + 1) * (1.0f / 256.0f));
}
__device__ __forceinline__ float row_coef(int m) {
    return c_wk[m % 15] * (1.0f / 256.0f);
}
__device__ __forceinline__ void cp16(uint32_t dst, const float* src) {
    asm volatile("cp.async.cg.shared.global [%0], [%1], 16;" :: "r"(dst), "l"(src));
}
__device__ __forceinline__ void cp_commit() {
    asm volatile("cp.async.commit_group;" ::: "memory");
}
template<int N>
__device__ __forceinline__ void cp_wait() {
    asm volatile("cp.async.wait_group %0;" :: "n"(N) : "memory");
}
__device__ __forceinline__ void mma_tf32(float* d, const uint32_t* a, const uint32_t* b) {
    asm volatile(
        "mma.sync.aligned.m16n8k8.row.col.f32.tf32.tf32.f32 "
        "{%0,%1,%2,%3}, {%4,%5,%6,%7}, {%8,%9}, {%0,%1,%2,%3};"
        : "+f"(d[0]), "+f"(d[1]), "+f"(d[2]), "+f"(d[3])
        : "r"(a[0]), "r"(a[1]), "r"(a[2]), "r"(a[3]), "r"(b[0]), "r"(b[1]));
}

// ---------------- prep kernels ----------------
__global__ __launch_bounds__(256) void phi_gen(const float* __restrict__ freqs) {
    __shared__ float tile[32][33];
    const int d0 = blockIdx.x * 32, m0 = blockIdx.y * 32;
    const int tx = threadIdx.x, ty = threadIdx.y;
    float f = freqs[d0 + tx];
    #pragma unroll
    for (int r = 0; r < 4; r++) {
        int ml = ty + r * 8;
        int m = m0 + ml;
        float v = tf32r(sinf(row_t(m) * f));
        g_phi[(size_t)m * DD + d0 + tx] = v;
        tile[ml][tx] = v;
    }
    __syncthreads();
    #pragma unroll
    for (int r = 0; r < 4; r++) {
        int dl = ty + r * 8;
        g_phiT[(size_t)(d0 + dl) * NROWS + m0 + tx] = tile[tx][dl];
    }
}

__global__ __launch_bounds__(256) void wr_gen(const float* __restrict__ W) {
    size_t i = ((size_t)blockIdx.x * 256 + threadIdx.x) * 4;
    float4 v = *reinterpret_cast<const float4*>(W + i);
    v.x = tf32r(v.x); v.y = tf32r(v.y); v.z = tf32r(v.z); v.w = tf32r(v.w);
    *reinterpret_cast<float4*>(g_Wr + i) = v;
}

// ---------------- pipelined tf32 mma GEMM ----------------
// C[M,N] = A[M,K](K-major) @ B[K,N](N-major rows)
// 4 warps, warp tile 64x64 (mt=4 x nt=8 of m16n8k8)
template<int KTOT, bool EPI1>
__global__ void __launch_bounds__(NTHREADS, 2) gemm_mma(
    const float* __restrict__ gA, int ldA,
    const float* __restrict__ gB,
    const float* __restrict__ bias,
    const float* __restrict__ afreqs,
    float* __restrict__ outp)
{
    constexpr int KT = KTOT / BK;
    extern __shared__ float sm[];
    float* As = sm;                       // NSTAGE * A_STG
    float* Bs = sm + NSTAGE * A_STG;      // NSTAGE * B_STG

    const int tid = threadIdx.x;
    const int wid = tid >> 5, lane = tid & 31;
    const int wy = wid >> 1, wx = wid & 1;        // 2 x 2 warp grid
    const int r = lane >> 2, kq = lane & 3, gid = lane >> 2;
    const int bm = blockIdx.y * BM, bn = blockIdx.x * BN;

    float d[4][8][4];
    #pragma unroll
    for (int mt = 0; mt < 4; mt++)
        #pragma unroll
        for (int nt = 0; nt < 8; nt++)
            #pragma unroll
            for (int j = 0; j < 4; j++) d[mt][nt][j] = 0.0f;

    // ---- async stage loader (128 threads: 4 A chunks + 4 B chunks each) ----
    auto load_stage = [&](int kt, int slot) {
        const int k0 = kt * BK;
        float* Asl = As + slot * A_STG;
        float* Bsl = Bs + slot * B_STG;
        #pragma unroll
        for (int i = 0; i < 4; i++) {           // A: 512 chunks (128 rows x 4)
            int c = tid + i * NTHREADS;
            int row = c >> 2, col = c & 3;
            cp16(s2u(Asl + row * ASTRIDE + col * 4),
                 gA + (size_t)(bm + row) * ldA + k0 + col * 4);
        }
        #pragma unroll
        for (int i = 0; i < 4; i++) {           // B: 512 chunks (16 rows x 32)
            int c = tid + i * NTHREADS;
            int row = c >> 5, col = c & 31;
            cp16(s2u(Bsl + row * BSTRIDE + col * 4),
                 gB + (size_t)(k0 + row) * DD + bn + col * 4);
        }
    };

    #pragma unroll
    for (int s = 0; s < NSTAGE - 1; s++) { load_stage(s, s); cp_commit(); }

    #pragma unroll 1
    for (int kt = 0; kt < KT; kt++) {
        cp_wait<NSTAGE - 2>();
        __syncthreads();
        if (kt + NSTAGE - 1 < KT) load_stage(kt + NSTAGE - 1, (kt + NSTAGE - 1) & (NSTAGE - 1));
        cp_commit();

        const int slot = kt & (NSTAGE - 1);
        const float* Asl = As + slot * A_STG + (wy * 64) * ASTRIDE;
        const float* Bsl = Bs + slot * B_STG + wx * 64;

        #pragma unroll
        for (int kk = 0; kk < 2; kk++) {
            const int co = kk * 8;
            uint32_t bf[8][2];
            #pragma unroll
            for (int nt = 0; nt < 8; nt++) {
                int n = nt * 8 + gid;
                bf[nt][0] = __float_as_uint(Bsl[(co + kq)     * BSTRIDE + n]);
                bf[nt][1] = __float_as_uint(Bsl[(co + kq + 4) * BSTRIDE + n]);
            }
            #pragma unroll
            for (int mt = 0; mt < 4; mt++) {
                const float* ap = Asl + (mt * 16 + r) * ASTRIDE + co + kq;
                uint32_t af[4];
                af[0] = __float_as_uint(ap[0]);
                af[1] = __float_as_uint(ap[8 * ASTRIDE]);
                af[2] = __float_as_uint(ap[4]);
                af[3] = __float_as_uint(ap[8 * ASTRIDE + 4]);
                #pragma unroll
                for (int nt = 0; nt < 8; nt++) mma_tf32(d[mt][nt], af, bf[nt]);
            }
        }
    }

    // ---- epilogue ----
    #pragma unroll
    for (int mt = 0; mt < 4; mt++) {
        const int m0 = bm + wy * 64 + mt * 16 + r;
        #pragma unroll
        for (int h = 0; h < 2; h++) {
            const int m = m0 + h * 8;
            float t = 0.f, cf = 0.f;
            if (EPI1) { t = row_t(m); cf = row_coef(m); }
            #pragma unroll
            for (int nt = 0; nt < 8; nt++) {
                const int n = bn + wx * 64 + nt * 8 + 2 * kq;
                float v0 = d[mt][nt][2 * h], v1 = d[mt][nt][2 * h + 1];
                if (EPI1) {
                    float z0 = v0 + __ldg(bias + n);
                    float z1 = v1 + __ldg(bias + n + 1);
                    float t0 = tanhf(z0), t1 = tanhf(z1);
                    v0 = tf32r(cf * cosf(t * __ldg(afreqs + n))     * (1.0f - t0 * t0));
                    v1 = tf32r(cf * cosf(t * __ldg(afreqs + n + 1)) * (1.0f - t1 * t1));
                }
                *reinterpret_cast<float2*>(outp + (size_t)m * DD + n) = make_float2(v0, v1);
            }
        }
    }
}

// ---------------- host ----------------
extern "C" void kernel_launch(void* const* d_in, const int* in_sizes, int n_in,
                              void* d_out, int out_size) {
    const float* W      = (const float*)d_in[0];
    const float* bias   = (const float*)d_in[1];
    const float* freqs  = (const float*)d_in[2];
    const float* afreqs = (const float*)d_in[3];
    float* out = (float*)d_out;

    void* p_phi;  cudaGetSymbolAddress(&p_phi,  g_phi);
    void* p_phiT; cudaGetSymbolAddress(&p_phiT, g_phiT);
    void* p_Wr;   cudaGetSymbolAddress(&p_Wr,   g_Wr);
    void* p_g;    cudaGetSymbolAddress(&p_g,    g_g);

    cudaFuncSetAttribute(gemm_mma<DD, true>,     cudaFuncAttributeMaxDynamicSharedMemorySize, SMEM_BYTES);
    cudaFuncSetAttribute(gemm_mma<NROWS, false>, cudaFuncAttributeMaxDynamicSharedMemorySize, SMEM_BYTES);

    phi_gen<<<dim3(DD / 32, NROWS / 32), dim3(32, 8)>>>(freqs);
    wr_gen<<<(DD * DD) / (256 * 4), 256>>>(W);

    // GEMM1: z = phi @ W (+bias) -> g = coef*cos*(1-tanh^2)   [1920 x 4096]
    gemm_mma<DD, true><<<dim3(DD / BN, NROWS / BM), NTHREADS, SMEM_BYTES>>>(
        (const float*)p_phi, DD, (const float*)p_Wr, bias, afreqs, (float*)p_g);
    // GEMM2: out = phiT @ g   [4096 x 4096], K = 1920
    gemm_mma<NROWS, false><<<dim3(DD / BN, DD / BM), NTHREADS, SMEM_BYTES>>>(
        (const float*)p_phiT, NROWS, (const float*)p_g, bias, afreqs, out);

    (void)in_sizes; (void)n_in; (void)out_size;
}

// round 7
// speedup vs baseline: 2.1790x; 2.1790x over previous
#include <cuda_runtime.h>
#include <cuda_fp16.h>
#include <cstdint>
#include <cstddef>

#define DD 4096
#define NROWS 1920

#define BM 128
#define BN 128
#define BKH 32               // K per stage, in halves
#define NSTAGE 4
#define NTHREADS 256         // 8 warps, 2x4 grid of 64x32 warp tiles

#define ASTRIDE 40           // halves per A smem row (32 -> 40 = 80B, 5x16B granules: conflict-free)
#define BSTRIDE 136          // halves per B smem row (128 -> 136 = 272B, 17x16B granules: conflict-free)
#define A_STG (BM * ASTRIDE)   // 5120 halves
#define B_STG (BKH * BSTRIDE)  // 4352 halves
#define SMEM_HALVES (NSTAGE * (A_STG + B_STG))
#define SMEM_BYTES  (SMEM_HALVES * 2)   // 75776

#define GSCALE 4096.0f
#define INV_GSCALE (1.0f / 4096.0f)

__constant__ float c_nodes[15] = {
    0.20778495500789848f,  0.4058451513773972f,  0.5860872354676911f,
    0.7415311855993945f,   0.8648644233597691f,  0.9491079123427585f,
    0.9914553711208126f,  -0.9914553711208126f, -0.9491079123427585f,
   -0.8648644233597691f,  -0.7415311855993945f, -0.5860872354676911f,
   -0.4058451513773972f,  -0.20778495500789848f, 0.0f
};
__constant__ float c_wk[15] = {
    0.20443294007529889f, 0.19035057806478542f, 0.1690047266392679f,
    0.14065325971552592f, 0.10479001032225019f, 0.06309209262997856f,
    0.022935322010529224f, 0.022935322010529224f, 0.06309209262997856f,
    0.10479001032225019f, 0.14065325971552592f, 0.1690047266392679f,
    0.19035057806478542f, 0.20443294007529889f, 0.20948214108472782f
};

// Scratch (__device__ globals: allocation-free rule)
__device__ __align__(128) __half g_phi_h [(size_t)NROWS * DD];  // [m][k]
__device__ __align__(128) __half g_phiT_h[(size_t)DD * NROWS];  // [i][n]
__device__ __align__(128) __half g_W_h   [(size_t)DD * DD];     // [k][n]
__device__ __align__(128) __half g_g_h   [(size_t)NROWS * DD];  // [m][n], scaled by GSCALE

// ---------------- helpers ----------------
__device__ __forceinline__ uint32_t s2u(const void* p) {
    uint32_t a;
    asm("{ .reg .u64 t; cvta.to.shared.u64 t, %1; cvt.u32.u64 %0, t; }" : "=r"(a) : "l"(p));
    return a;
}
__device__ __forceinline__ float row_t(int m) {
    return fmaf(c_nodes[m % 15], 1.0f / 256.0f, (float)(2 * (m / 15) + 1) * (1.0f / 256.0f));
}
__device__ __forceinline__ float row_coef(int m) {
    return c_wk[m % 15] * (1.0f / 256.0f);
}
__device__ __forceinline__ void cp16(uint32_t dst, const void* src) {
    asm volatile("cp.async.cg.shared.global [%0], [%1], 16;" :: "r"(dst), "l"(src));
}
__device__ __forceinline__ void cp_commit() {
    asm volatile("cp.async.commit_group;" ::: "memory");
}
template<int N>
__device__ __forceinline__ void cp_wait() {
    asm volatile("cp.async.wait_group %0;" :: "n"(N) : "memory");
}
__device__ __forceinline__ void ldsm_x4(uint32_t* r, uint32_t addr) {
    asm volatile("ldmatrix.sync.aligned.m8n8.x4.shared.b16 {%0,%1,%2,%3}, [%4];"
                 : "=r"(r[0]), "=r"(r[1]), "=r"(r[2]), "=r"(r[3]) : "r"(addr));
}
__device__ __forceinline__ void ldsm_x4_t(uint32_t* r, uint32_t addr) {
    asm volatile("ldmatrix.sync.aligned.m8n8.x4.trans.shared.b16 {%0,%1,%2,%3}, [%4];"
                 : "=r"(r[0]), "=r"(r[1]), "=r"(r[2]), "=r"(r[3]) : "r"(addr));
}
__device__ __forceinline__ void mma_f16(float* d, const uint32_t* a, const uint32_t* b) {
    asm volatile(
        "mma.sync.aligned.m16n8k16.row.col.f32.f16.f16.f32 "
        "{%0,%1,%2,%3}, {%4,%5,%6,%7}, {%8,%9}, {%0,%1,%2,%3};"
        : "+f"(d[0]), "+f"(d[1]), "+f"(d[2]), "+f"(d[3])
        : "r"(a[0]), "r"(a[1]), "r"(a[2]), "r"(a[3]), "r"(b[0]), "r"(b[1]));
}

// ---------------- prep kernels ----------------
// phi[m][d] = half(sin(t_m*freqs[d])), and phiT[d][m] (identical rounding)
__global__ __launch_bounds__(256) void phi_gen(const float* __restrict__ freqs) {
    __shared__ float tile[32][33];
    const int d0 = blockIdx.x * 32, m0 = blockIdx.y * 32;
    const int tx = threadIdx.x, ty = threadIdx.y;
    float f = freqs[d0 + tx];
    #pragma unroll
    for (int r = 0; r < 4; r++) {
        int ml = ty + r * 8;
        int m = m0 + ml;
        float v = sinf(row_t(m) * f);
        g_phi_h[(size_t)m * DD + d0 + tx] = __float2half_rn(v);
        tile[ml][tx] = v;
    }
    __syncthreads();
    #pragma unroll
    for (int r = 0; r < 4; r++) {
        int dl = ty + r * 8;
        g_phiT_h[(size_t)(d0 + dl) * NROWS + m0 + tx] = __float2half_rn(tile[tx][dl]);
    }
}

// W fp32 -> fp16 (same layout), 8 elems/thread
__global__ __launch_bounds__(256) void wh_gen(const float* __restrict__ W) {
    size_t i = ((size_t)blockIdx.x * 256 + threadIdx.x) * 8;
    float4 v0 = *reinterpret_cast<const float4*>(W + i);
    float4 v1 = *reinterpret_cast<const float4*>(W + i + 4);
    __half2 h[4];
    h[0] = __floats2half2_rn(v0.x, v0.y);
    h[1] = __floats2half2_rn(v0.z, v0.w);
    h[2] = __floats2half2_rn(v1.x, v1.y);
    h[3] = __floats2half2_rn(v1.z, v1.w);
    *reinterpret_cast<uint4*>(g_W_h + i) = *reinterpret_cast<uint4*>(h);
}

// ---------------- pipelined fp16 mma GEMM ----------------
// C[M,N] = A[M,K](K-major halves) @ B[K,N](N-major rows, halves)
// 8 warps (2x4), warp tile 64x32 (mt=4 x nt=4 of m16n8k16)
template<int KTOT, bool EPI1>
__global__ void __launch_bounds__(NTHREADS, 2) gemm_mma(
    const __half* __restrict__ gA, int ldA,
    const __half* __restrict__ gB,
    const float* __restrict__ bias,
    const float* __restrict__ afreqs,
    void* __restrict__ outp)
{
    constexpr int KT = KTOT / BKH;
    extern __shared__ __half sm[];
    __half* As = sm;                       // NSTAGE * A_STG
    __half* Bs = sm + NSTAGE * A_STG;      // NSTAGE * B_STG

    const int tid = threadIdx.x;
    const int wid = tid >> 5, lane = tid & 31;
    const int wy = wid >> 2, wx = wid & 3;        // 2 x 4 warp grid
    const int r = lane >> 2, kq = lane & 3;
    const int bm = blockIdx.y * BM, bn = blockIdx.x * BN;

    // ldmatrix per-lane offsets (in halves)
    const int a_ml = lane & 15, a_kh = (lane >> 4) * 8;       // A x4: (m0-7,k0-7)(m8-15,k0-7)(m0-7,k8-15)(m8-15,k8-15)
    const int b_kl = lane & 15, b_nl = (lane >> 4) * 8;       // B x4.trans: (k0-7,n0-7)(k8-15,n0-7)(k0-7,n8-15)(k8-15,n8-15)

    float d[4][4][4];
    #pragma unroll
    for (int mt = 0; mt < 4; mt++)
        #pragma unroll
        for (int nt = 0; nt < 4; nt++)
            #pragma unroll
            for (int j = 0; j < 4; j++) d[mt][nt][j] = 0.0f;

    // ---- async stage loader: A 512 chunks (128 rows x 4x16B), B 512 chunks (32 rows x 16x16B) ----
    auto load_stage = [&](int kt, int slot) {
        const int k0 = kt * BKH;
        __half* Asl = As + slot * A_STG;
        __half* Bsl = Bs + slot * B_STG;
        #pragma unroll
        for (int i = 0; i < 2; i++) {
            int c = tid + i * NTHREADS;
            int row = c >> 2, col = c & 3;
            cp16(s2u(Asl + row * ASTRIDE + col * 8),
                 gA + (size_t)(bm + row) * ldA + k0 + col * 8);
        }
        #pragma unroll
        for (int i = 0; i < 2; i++) {
            int c = tid + i * NTHREADS;
            int row = c >> 4, col = c & 15;
            cp16(s2u(Bsl + row * BSTRIDE + col * 8),
                 gB + (size_t)(k0 + row) * DD + bn + col * 8);
        }
    };

    #pragma unroll
    for (int s = 0; s < NSTAGE - 1; s++) { load_stage(s, s); cp_commit(); }

    #pragma unroll 1
    for (int kt = 0; kt < KT; kt++) {
        cp_wait<NSTAGE - 2>();
        __syncthreads();
        if (kt + NSTAGE - 1 < KT) load_stage(kt + NSTAGE - 1, (kt + NSTAGE - 1) & (NSTAGE - 1));
        cp_commit();

        const int slot = kt & (NSTAGE - 1);
        const uint32_t sA = s2u(As + slot * A_STG) + ((wy * 64 + a_ml) * ASTRIDE + a_kh) * 2;
        const uint32_t sB = s2u(Bs + slot * B_STG) + (b_kl * BSTRIDE + wx * 32 + b_nl) * 2;

        #pragma unroll
        for (int kk = 0; kk < 2; kk++) {
            uint32_t af[4][4];
            #pragma unroll
            for (int mt = 0; mt < 4; mt++)
                ldsm_x4(af[mt], sA + (mt * 16 * ASTRIDE + kk * 16) * 2);
            uint32_t bf[4][2];
            #pragma unroll
            for (int ntp = 0; ntp < 2; ntp++) {
                uint32_t br[4];
                ldsm_x4_t(br, sB + (kk * 16 * BSTRIDE + ntp * 16) * 2);
                bf[2 * ntp][0] = br[0]; bf[2 * ntp][1] = br[1];
                bf[2 * ntp + 1][0] = br[2]; bf[2 * ntp + 1][1] = br[3];
            }
            #pragma unroll
            for (int mt = 0; mt < 4; mt++)
                #pragma unroll
                for (int nt = 0; nt < 4; nt++)
                    mma_f16(d[mt][nt], af[mt], bf[nt]);
        }
    }

    // ---- epilogue: lane holds c[m=r(+8)][n=2kq(+1)] per (mt,nt) ----
    #pragma unroll
    for (int mt = 0; mt < 4; mt++) {
        const int m0 = bm + wy * 64 + mt * 16 + r;
        #pragma unroll
        for (int h = 0; h < 2; h++) {
            const int m = m0 + h * 8;
            float t = 0.f, cf = 0.f;
            if (EPI1) { t = row_t(m); cf = row_coef(m); }
            #pragma unroll
            for (int nt = 0; nt < 4; nt++) {
                const int n = bn + wx * 32 + nt * 8 + 2 * kq;
                float v0 = d[mt][nt][2 * h], v1 = d[mt][nt][2 * h + 1];
                if (EPI1) {
                    float z0 = v0 + __ldg(bias + n);
                    float z1 = v1 + __ldg(bias + n + 1);
                    float t0 = tanhf(z0), t1 = tanhf(z1);
                    v0 = cf * cosf(t * __ldg(afreqs + n))     * (1.0f - t0 * t0) * GSCALE;
                    v1 = cf * cosf(t * __ldg(afreqs + n + 1)) * (1.0f - t1 * t1) * GSCALE;
                    __half2 hv = __floats2half2_rn(v0, v1);
                    *reinterpret_cast<__half2*>((__half*)outp + (size_t)m * DD + n) = hv;
                } else {
                    float2 fv = make_float2(v0 * INV_GSCALE, v1 * INV_GSCALE);
                    *reinterpret_cast<float2*>((float*)outp + (size_t)m * DD + n) = fv;
                }
            }
        }
    }
}

// ---------------- host ----------------
extern "C" void kernel_launch(void* const* d_in, const int* in_sizes, int n_in,
                              void* d_out, int out_size) {
    const float* W      = (const float*)d_in[0];
    const float* bias   = (const float*)d_in[1];
    const float* freqs  = (const float*)d_in[2];
    const float* afreqs = (const float*)d_in[3];

    void* p_phi;  cudaGetSymbolAddress(&p_phi,  g_phi_h);
    void* p_phiT; cudaGetSymbolAddress(&p_phiT, g_phiT_h);
    void* p_W;    cudaGetSymbolAddress(&p_W,    g_W_h);
    void* p_g;    cudaGetSymbolAddress(&p_g,    g_g_h);

    cudaFuncSetAttribute(gemm_mma<DD, true>,     cudaFuncAttributeMaxDynamicSharedMemorySize, SMEM_BYTES);
    cudaFuncSetAttribute(gemm_mma<NROWS, false>, cudaFuncAttributeMaxDynamicSharedMemorySize, SMEM_BYTES);

    phi_gen<<<dim3(DD / 32, NROWS / 32), dim3(32, 8)>>>(freqs);
    wh_gen<<<(DD * DD) / (256 * 8), 256>>>(W);

    // GEMM1: z = phi @ W (+bias) -> g = coef*cos*(1-tanh^2), scaled, fp16   [1920 x 4096]
    gemm_mma<DD, true><<<dim3(DD / BN, NROWS / BM), NTHREADS, SMEM_BYTES>>>(
        (const __half*)p_phi, DD, (const __half*)p_W, bias, afreqs, p_g);
    // GEMM2: out = phiT @ g * 1/GSCALE   [4096 x 4096], K = 1920
    gemm_mma<NROWS, false><<<dim3(DD / BN, DD / BM), NTHREADS, SMEM_BYTES>>>(
        (const __half*)p_phiT, NROWS, (const __half*)p_g, bias, afreqs, d_out);

    (void)in_sizes; (void)n_in; (void)out_size;
}